// round 15
// baseline (speedup 1.0000x reference)
#include <cuda_runtime.h>
#include <cuda_bf16.h>
#include <cuda_fp16.h>
#include <cstdint>

// x(4,256,64,64), p_w(18,256,3,3), p_b(18), conv_w(256,256,3,3) -> out(4,256,64,64)
#define NB   4
#define NH   64
#define NW   64
#define KTOT 2304   // 256*9

__device__ float g_off[NB * 18 * NH * NW];
__device__ __align__(16) __half g_whi[256 * KTOT];   // [oc][k] fp16(W)
// padded fp16 image, 2 parity copies of paired columns:
// [b][ch][copy(2)][row(66)][word(34)] u32 ; copyE word j = cols (2j,2j+1),
// copyO word j = cols (2j+1,2j+2). Rows/cols 0 & 65 are the zero pad ring.
#define CH_WORDS 4488   // 2*66*34
__device__ __align__(16) uint32_t g_xh[NB * 256 * CH_WORDS];

// ---------------------------------------------------------------------------
// Fused pre-kernel: blocks [0,256) offset conv | [256,1280) x->fp16 image |
//                   [1280,3584) W->fp16
// ---------------------------------------------------------------------------
__global__ void __launch_bounds__(256) k_pre(const float* __restrict__ x,
                                             const float* __restrict__ pw,
                                             const float* __restrict__ pb,
                                             const float* __restrict__ cw) {
    __shared__ __align__(16) float patch[4][3][68];
    __shared__ __align__(16) float ws[4][9][20];
    __shared__ float red[4][64][18];
    __shared__ __align__(4) unsigned short xh[4096];

    int blk = blockIdx.x;
    int tid = threadIdx.x;

    if (blk >= 1280) {
        // ---- W convert: 2304 blocks x 256 ----
        int e = (blk - 1280) * 256 + tid;
        g_whi[e] = __float2half_rn(cw[e]);
        return;
    }
    if (blk >= 256) {
        // ---- x -> padded fp16 paired-column image, one block per (b,ch) ----
        int bc = blk - 256;                    // b*256 + ch
        const float* xc = x + (size_t)bc * 4096;
        for (int i = tid; i < 4096; i += 256)
            xh[i] = __half_as_ushort(__float2half_rn(xc[i]));
        __syncthreads();
        uint32_t* dst = g_xh + (size_t)bc * CH_WORDS;
        for (int word = tid; word < CH_WORDS; word += 256) {
            int copy = word / 2244;
            int rw   = word - copy * 2244;
            int row  = rw / 34;
            int j    = rw - row * 34;
            int p0   = 2 * j + copy;
            uint32_t h0 = 0, h1 = 0;
            if (row >= 1 && row <= 64) {
                if (p0 >= 1 && p0 <= 64)     h0 = xh[(row - 1) * 64 + (p0 - 1)];
                if (p0 + 1 >= 1 && p0 + 1 <= 64) h1 = xh[(row - 1) * 64 + p0];
            }
            dst[word] = h0 | (h1 << 16);
        }
        return;
    }

    // ---- offset conv: blocks [0,256) ----
    int b = blk >> 6;
    int h = blk & 63;
    int g   = tid >> 6;
    int pix = tid & 63;

    float acc[20];
#pragma unroll
    for (int i = 0; i < 20; i++) acc[i] = 0.f;

    const float* xb = x + ((size_t)b << 20);

    for (int cc = 0; cc < 64; cc++) {
        for (int l = tid; l < 4 * 3 * 66; l += 256) {
            int gg  = l / 198;
            int rem = l - gg * 198;
            int r   = rem / 66;
            int wc  = rem - r * 66;
            int y   = h + r - 1;
            int xw  = wc - 1;
            float v = 0.f;
            if (y >= 0 && y < NH && xw >= 0 && xw < NW)
                v = xb[((gg * 64 + cc) << 12) + (y << 6) + xw];
            patch[gg][r][wc] = v;
        }
        for (int l = tid; l < 720; l += 256) {
            int gg  = l / 180;
            int rem = l - gg * 180;
            int n   = rem / 20;
            int oc  = rem - n * 20;
            float v = 0.f;
            if (oc < 18) v = pw[oc * KTOT + (gg * 64 + cc) * 9 + n];
            ws[gg][n][oc] = v;
        }
        __syncthreads();

#pragma unroll
        for (int ky = 0; ky < 3; ky++) {
#pragma unroll
            for (int kx = 0; kx < 3; kx++) {
                float s = patch[g][ky][pix + kx];
                int n = ky * 3 + kx;
#pragma unroll
                for (int q = 0; q < 5; q++) {
                    float4 w4 = *(const float4*)&ws[g][n][q * 4];
                    acc[q * 4 + 0] += w4.x * s;
                    acc[q * 4 + 1] += w4.y * s;
                    acc[q * 4 + 2] += w4.z * s;
                    acc[q * 4 + 3] += w4.w * s;
                }
            }
        }
        __syncthreads();
    }

#pragma unroll
    for (int i = 0; i < 18; i++) red[g][pix][i] = acc[i];
    __syncthreads();

    for (int e = tid; e < 64 * 18; e += 256) {
        int p2 = e / 18;
        int oc = e - p2 * 18;
        float v = red[0][p2][oc] + red[1][p2][oc] + red[2][p2][oc] + red[3][p2][oc] + pb[oc];
        g_off[((b * 18 + oc) << 12) + (h << 6) + p2] = v;
    }
}

// ---------------------------------------------------------------------------
// Kernel 2: warp-level fp16 mma.sync implicit GEMM + paired-load sampling
// CTA: 256 oc x 64 px (one row), 256 thr = 8 warps (4M x 2N), warp tile 64x32.
// grid = 256, 2 CTAs/SM. K=2304 in 36 chunks of 64. smem rows 144B.
// ---------------------------------------------------------------------------
#define OFF_TABI 0          // uint[576]       2304 B (utop | ubot<<16)
#define OFF_TABW 2304       // float4[576]     9216 B
#define OFF_W    11520      // 2 buf x 36864 (256 rows x 144B)
#define WBUF     36864
#define OFF_S    85248      // 2 buf x 9216 (64 rows x 144B)
#define SBUF     9216
#define SMEM_SZ  103680
#define RSTRIDE  144        // bytes per k-row

__device__ __forceinline__ void cp16(uint32_t smem_dst, const void* gsrc) {
    asm volatile("cp.async.cg.shared.global [%0], [%1], 16;" ::"r"(smem_dst), "l"(gsrc));
}
__device__ __forceinline__ void ldsm4(uint32_t a[4], uint32_t addr) {
    asm volatile("ldmatrix.sync.aligned.m8n8.x4.shared.b16 {%0,%1,%2,%3}, [%4];"
                 : "=r"(a[0]), "=r"(a[1]), "=r"(a[2]), "=r"(a[3]) : "r"(addr));
}
__device__ __forceinline__ void ldsm2(uint32_t a[2], uint32_t addr) {
    asm volatile("ldmatrix.sync.aligned.m8n8.x2.shared.b16 {%0,%1}, [%2];"
                 : "=r"(a[0]), "=r"(a[1]) : "r"(addr));
}
__device__ __forceinline__ void mma16816(float d[4], const uint32_t a[4], const uint32_t b[2]) {
    asm volatile(
        "mma.sync.aligned.m16n8k16.row.col.f32.f16.f16.f32 "
        "{%0,%1,%2,%3}, {%4,%5,%6,%7}, {%8,%9}, {%0,%1,%2,%3};"
        : "+f"(d[0]), "+f"(d[1]), "+f"(d[2]), "+f"(d[3])
        : "r"(a[0]), "r"(a[1]), "r"(a[2]), "r"(a[3]), "r"(b[0]), "r"(b[1]));
}

// load W chunk ch (64 k): [256 oc][144B rows]; 2048 16B chunks / 256 thr
__device__ __forceinline__ void load_W(uint32_t wbase, int ch, int tid) {
#pragma unroll
    for (int j = 0; j < 8; j++) {
        int idx = tid + (j << 8);       // 0..2047
        int oc  = idx >> 3;
        int c16 = idx & 7;
        cp16(wbase + oc * RSTRIDE + c16 * 16,
             g_whi + (size_t)oc * KTOT + ch * 64 + c16 * 8);
    }
}

// produce S chunk ch: fp16 [64 pix][144B rows]; 2048 word-pairs / 256 thr
__device__ __forceinline__ void produce_S(char* sbase, const uint32_t* __restrict__ xhb,
                                          const uint32_t* tabi, const float4* tabw,
                                          int ch, int tid) {
#pragma unroll
    for (int j = 0; j < 8; j++) {
        int idx = tid + (j << 8);       // 0..2047
        int kk2 = idx >> 6;             // 0..31
        int pix = idx & 63;
        uint32_t hbits = 0;
#pragma unroll
        for (int u = 0; u < 2; u++) {
            int k  = ch * 64 + kk2 * 2 + u;
            int ci = k / 9;
            int n  = k - ci * 9;
            uint32_t id = tabi[pix * 9 + n];
            float4  wg  = tabw[pix * 9 + n];
            const uint32_t* xc = xhb + (size_t)ci * CH_WORDS;
            uint32_t top = xc[id & 0xffffu];
            uint32_t bot = xc[id >> 16];
            float2 ft = __half22float2(*(__half2*)&top);
            float2 fb = __half22float2(*(__half2*)&bot);
            float s = wg.x * ft.x + wg.y * ft.y + wg.z * fb.x + wg.w * fb.y;
            hbits |= (uint32_t)__half_as_ushort(__float2half_rn(s)) << (u * 16);
        }
        *(uint32_t*)(sbase + pix * RSTRIDE + kk2 * 4) = hbits;
    }
}

__global__ void __launch_bounds__(256, 2) k_main(float* __restrict__ out) {
    extern __shared__ __align__(16) char sm[];
    uint32_t smb = (uint32_t)__cvta_generic_to_shared(sm);
    int tid  = threadIdx.x;
    int wid  = tid >> 5;              // 0..7
    int lane = tid & 31;
    int wm   = wid >> 1;              // 0..3 -> oc base wm*64
    int wn   = wid & 1;               // 0..1 -> pix base wn*32
    int b    = blockIdx.x >> 6;
    int h    = blockIdx.x & 63;
    const uint32_t* xhb = g_xh + (size_t)b * 256 * CH_WORDS;

    uint32_t* tabi = (uint32_t*)(sm + OFF_TABI);
    float4*   tabw = (float4*)(sm + OFF_TABW);

    // ---- bilinear tables: 64 pixels x 9 taps, paired-load form ----
    for (int e = tid; e < 576; e += 256) {
        int pix = e / 9;
        int n   = e - pix * 9;
        int w   = pix;
        int gbase = ((b * 18 + n) << 12) + (h << 6) + w;
        float offy = g_off[gbase];
        float offx = g_off[gbase + (9 << 12)];
        int ky = n / 3;
        int kx = n - ky * 3;
        float py = (float)(h + ky) + offy;     // padded coords
        float px = (float)(w + kx) + offx;
        float fy = floorf(py), fx = floorf(px);
        float qlty = fminf(fmaxf(fy, 0.f), 65.f);
        float qrby = fminf(fmaxf(fy + 1.f, 0.f), 65.f);
        float qltx = fminf(fmaxf(fx, 0.f), 65.f);
        float qrbx = fminf(fmaxf(fx + 1.f, 0.f), 65.f);
        float pyc = fminf(fmaxf(py, 0.f), 65.f);
        float pxc = fminf(fmaxf(px, 0.f), 65.f);
        float dly = 1.f + qlty - pyc, dry = 1.f - qrby + pyc;
        float dlx = 1.f + qltx - pxc, drx = 1.f - qrbx + pxc;
        float g_lt = dly * dlx, g_rb = dry * drx, g_lb = dly * drx, g_rt = dry * dlx;
        int ily = (int)qlty, iry = (int)qrby, ilx = (int)qltx, irx = (int)qrbx;
        bool foldx = (irx == ilx);
        float w_lo_t = g_lt + (foldx ? g_lb : 0.f);
        float w_hi_t = foldx ? 0.f : g_lb;
        float w_lo_b = g_rt + (foldx ? g_rb : 0.f);
        float w_hi_b = foldx ? 0.f : g_rb;
        int cpy = ilx & 1;
        int wj  = (ilx - cpy) >> 1;
        uint32_t utop = (uint32_t)(cpy * 2244 + ily * 34 + wj);
        uint32_t ubot = (uint32_t)(cpy * 2244 + iry * 34 + wj);
        tabi[e] = utop | (ubot << 16);
        tabw[e] = make_float4(w_lo_t, w_hi_t, w_lo_b, w_hi_b);
    }
    __syncthreads();

    // ---- prologue: chunk 0 into buffer 0 ----
    load_W(smb + OFF_W, 0, tid);
    asm volatile("cp.async.commit_group;" ::: "memory");
    produce_S(sm + OFF_S, xhb, tabi, tabw, 0, tid);

    float d[4][4][4];
#pragma unroll
    for (int mt = 0; mt < 4; mt++)
#pragma unroll
        for (int nt = 0; nt < 4; nt++)
#pragma unroll
            for (int q = 0; q < 4; q++) d[mt][nt][q] = 0.f;

    // ---- main loop: 36 K-chunks of 64 ----
    for (int ch = 0; ch < 36; ch++) {
        asm volatile("cp.async.wait_group 0;" ::: "memory");
        __syncthreads();

        uint32_t wbase = smb + OFF_W + (ch & 1) * WBUF;
        uint32_t sbase = smb + OFF_S + (ch & 1) * SBUF;

        if (ch + 1 < 36) {
            int nb2 = (ch + 1) & 1;
            load_W(smb + OFF_W + nb2 * WBUF, ch + 1, tid);
            asm volatile("cp.async.commit_group;" ::: "memory");
            produce_S(sm + OFF_S + nb2 * SBUF, xhb, tabi, tabw, ch + 1, tid);
        }

#pragma unroll
        for (int kk = 0; kk < 4; kk++) {
            uint32_t bh[4][2];
#pragma unroll
            for (int nt = 0; nt < 4; nt++) {
                uint32_t baddr = sbase + (wn * 32 + nt * 8 + (lane & 7)) * RSTRIDE
                               + (kk * 16 + ((lane >> 3) & 1) * 8) * 2;
                ldsm2(bh[nt], baddr);
            }
#pragma unroll
            for (int mt = 0; mt < 4; mt++) {
                uint32_t aaddr = wbase + (wm * 64 + mt * 16 + (lane & 15)) * RSTRIDE
                               + (kk * 16 + (lane >> 4) * 8) * 2;
                uint32_t ah[4];
                ldsm4(ah, aaddr);
#pragma unroll
                for (int nt = 0; nt < 4; nt++)
                    mma16816(d[mt][nt], ah, bh[nt]);
            }
        }
    }

    // ---- epilogue: store accumulators ----
    int g4 = lane >> 2;
    int t4 = lane & 3;
#pragma unroll
    for (int mt = 0; mt < 4; mt++) {
#pragma unroll
        for (int nt = 0; nt < 4; nt++) {
            int w = wn * 32 + nt * 8 + t4 * 2;
            int oc0 = wm * 64 + mt * 16 + g4;
            float* p0 = out + ((size_t)b << 20) + ((size_t)oc0 << 12) + (h << 6) + w;
            *(float2*)p0 = make_float2(d[mt][nt][0], d[mt][nt][1]);
            float* p1 = p0 + (8 << 12);   // oc0 + 8
            *(float2*)p1 = make_float2(d[mt][nt][2], d[mt][nt][3]);
        }
    }
}

// ---------------------------------------------------------------------------
extern "C" void kernel_launch(void* const* d_in, const int* in_sizes, int n_in,
                              void* d_out, int out_size) {
    const float* x  = (const float*)d_in[0];
    const float* pw = (const float*)d_in[1];
    const float* pb = (const float*)d_in[2];
    const float* cw = (const float*)d_in[3];
    float* out = (float*)d_out;

    cudaFuncSetAttribute(k_main, cudaFuncAttributeMaxDynamicSharedMemorySize, SMEM_SZ);

    k_pre<<<3584, 256>>>(x, pw, pb, cw);
    k_main<<<256, 256, SMEM_SZ>>>(out);
}